// round 16
// baseline (speedup 1.0000x reference)
#include <cuda_runtime.h>
#include <cuda_bf16.h>
#include <stdint.h>

#define TN 2000
#define UN 50000
#define TF 16
#define OUTC (TF + 36)
#define NF 40                   // padded features: 0..35 emb, 36 count, 37..39 zero
#define KPAD 50176              // mult of 64
#define KT2 64                  // K per pipeline stage
#define NST_TOT (KPAD / KT2)    // 784
#define MB 128                  // M per CTA (4 warps x m32)
#define NMB 16
#define TPAD (NMB * MB)         // 2048
#define NSPLIT 18               // grid = 288 CTAs ~ 2/SM
#define NTHR 128
#define ASTR 72                              // A row stride (ints): conflict-free
#define ASTAGE_B (128 * ASTR * 4)            // 36864 B
#define BSTR 40                              // B row stride (words): conflict-free
#define BSTAGE_B (NF * BSTR * 4)             // 6400 B
#define SMEM_TOTAL (2 * (ASTAGE_B + BSTAGE_B))   // 86528 B

// ---------------- device scratch (static, zero-init) ----------------
__device__ __nv_bfloat16 g_UT[(size_t)NF * KPAD];   // paired-word layout per 64k block
__device__ float g_part[(size_t)NSPLIT * TPAD * NF];
__device__ unsigned g_done[NMB];                    // zero-init; self-cleaning tickets

__device__ __forceinline__ uint32_t smem_u32(const void* p) {
    uint32_t a;
    asm("{ .reg .u64 t; cvta.to.shared.u64 t, %1; cvt.u32.u64 %0, t; }" : "=r"(a) : "l"(p));
    return a;
}
__device__ __forceinline__ void mma16816(float* c, uint32_t a0, uint32_t a1,
                                         uint32_t a2, uint32_t a3,
                                         uint32_t b0, uint32_t b1) {
    asm volatile("mma.sync.aligned.m16n8k16.row.col.f32.bf16.bf16.f32 "
                 "{%0,%1,%2,%3}, {%4,%5,%6,%7}, {%8,%9}, {%0,%1,%2,%3};"
                 : "+f"(c[0]), "+f"(c[1]), "+f"(c[2]), "+f"(c[3])
                 : "r"(a0), "r"(a1), "r"(a2), "r"(a3), "r"(b0), "r"(b1));
}
__device__ __forceinline__ uint32_t pk(int2 m) {
    return (uint32_t)(m.x + (m.y << 16)) * 0x3F80u;
}

// ---------------- prep: R6 exact (frozen) ----------------
__global__ void prep_kernel(const unsigned int* __restrict__ us,
                            const float* __restrict__ e0, const float* __restrict__ e1,
                            const float* __restrict__ e2, const float* __restrict__ e3,
                            const float* __restrict__ e4, const float* __restrict__ e5) {
    __shared__ float sT[NF * 64];
    int u0 = blockIdx.x * 64;
    int tid = threadIdx.x;
    if (tid < 64) {
        int u = u0 + tid;
        if (u < UN) {
            unsigned probe = 0;
#pragma unroll
            for (int w = 1; w < 32; w += 2) probe |= us[w];
            bool is64 = (probe == 0u);   // int64 serialization -> zero high words
            const float* tabs[6] = {e0, e1, e2, e3, e4, e5};
#pragma unroll
            for (int i = 0; i < 6; i++) {
                int elem = u * 6 + i;
                unsigned idx = us[is64 ? (2 * elem) : elem];
                const float* row = tabs[i] + (size_t)idx * 6;
#pragma unroll
                for (int j = 0; j < 6; j++) sT[(i * 6 + j) * 64 + tid] = row[j];
            }
            sT[36 * 64 + tid] = 1.0f;
        } else {
#pragma unroll
            for (int f = 0; f < 37; f++) sT[f * 64 + tid] = 0.0f;
        }
        sT[37 * 64 + tid] = 0.0f;
        sT[38 * 64 + tid] = 0.0f;
        sT[39 * 64 + tid] = 0.0f;
    }
    __syncthreads();
    for (int idx = tid; idx < NF * 32; idx += blockDim.x) {
        int f = idx >> 5, p = idx & 31;
        int wp = ((p >> 3) << 3) + ((p & 3) << 1) + ((p >> 2) & 1);
        __nv_bfloat162 v = __floats2bfloat162_rn(sT[f * 64 + 2 * p], sT[f * 64 + 2 * p + 1]);
        *(__nv_bfloat162*)(&g_UT[(size_t)f * KPAD + u0 + 2 * wp]) = v;
    }
}

// ---------------- accum helpers: R6 exact (frozen) ----------------
__device__ __forceinline__ void issue_stage(uint32_t smb, int s, int k0,
                                            const int* __restrict__ tum,
                                            int t0, int tid) {
    uint32_t aB = smb + s * ASTAGE_B;
    uint32_t bB = smb + 2 * ASTAGE_B + s * BSTAGE_B;
#pragma unroll
    for (int i = 0; i < 16; i++) {
        int q = tid + i * NTHR;
        int r = q >> 4;
        int c = (q & 15) << 2;
        uint32_t dst = aB + (uint32_t)r * (ASTR * 4) + (uint32_t)(q & 15) * 16u;
        const int* src = tum + (size_t)(t0 + r) * UN + (k0 + c);
        uint32_t sz = ((t0 + r) < TN && (k0 + c) < UN) ? 16u : 0u;
        asm volatile("cp.async.cg.shared.global [%0], [%1], 16, %2;"
                     :: "r"(dst), "l"(src), "r"(sz));
    }
#pragma unroll
    for (int i = 0; i < 3; i++) {
        int q = tid + i * NTHR;
        if (q < NF * 8) {
            int r = q >> 3;
            uint32_t dst = bB + (uint32_t)r * (BSTR * 4) + (uint32_t)(q & 7) * 16u;
            const __nv_bfloat16* src = g_UT + (size_t)r * KPAD + k0 + (q & 7) * 8;
            asm volatile("cp.async.cg.shared.global [%0], [%1], 16, 16;"
                         :: "r"(dst), "l"(src));
        }
    }
}

__device__ __forceinline__ void compute_stage(const char* sm, int s, float acc[2][5][4],
                                              int w, int g, int cc) {
    const int* aP = (const int*)(sm + s * ASTAGE_B);
    const uint32_t* bP = (const uint32_t*)(sm + 2 * ASTAGE_B + s * BSTAGE_B);
    const int rowA = (32 * w + g) * ASTR + 2 * cc;
#pragma unroll
    for (int ks = 0; ks < 4; ks++) {
        uint32_t bf[10];
        const uint32_t* bb = bP + g * BSTR + ks * 8 + cc * 2;
#pragma unroll
        for (int nb = 0; nb < 5; nb++) {
            uint2 v = *(const uint2*)(bb + nb * 8 * BSTR);
            bf[2 * nb] = v.x;
            bf[2 * nb + 1] = v.y;
        }
#pragma unroll
        for (int mh = 0; mh < 2; mh++) {
            const int* p0 = aP + rowA + mh * 16 * ASTR + 16 * ks;
            int2 x0 = *(const int2*)(p0);
            int2 x2 = *(const int2*)(p0 + 8);
            int2 x1 = *(const int2*)(p0 + 8 * ASTR);
            int2 x3 = *(const int2*)(p0 + 8 * ASTR + 8);
            uint32_t a0 = pk(x0), a1 = pk(x1), a2 = pk(x2), a3 = pk(x3);
#pragma unroll
            for (int nb = 0; nb < 5; nb++)
                mma16816(acc[mh][nb], a0, a1, a2, a3, bf[2 * nb], bf[2 * nb + 1]);
        }
    }
}

__global__ void __launch_bounds__(NTHR, 2) accum_kernel(const int* __restrict__ tum,
                                                        const float* __restrict__ T_static,
                                                        float* __restrict__ out) {
    extern __shared__ char sm[];
    __shared__ unsigned s_last;
    const int tid = threadIdx.x;
    const int w = tid >> 5, lane = tid & 31;
    const int g = lane >> 2, cc = lane & 3;
    const int mb = blockIdx.x & (NMB - 1);
    const int sp = blockIdx.x >> 4;
    const int t0 = mb * MB;
    const uint32_t smb = smem_u32(sm);

    const int J = (NST_TOT - sp + NSPLIT - 1) / NSPLIT;

    float acc[2][5][4];
#pragma unroll
    for (int mh = 0; mh < 2; mh++)
#pragma unroll
        for (int nb = 0; nb < 5; nb++)
#pragma unroll
            for (int q = 0; q < 4; q++) acc[mh][nb][q] = 0.0f;

    issue_stage(smb, 0, sp * KT2, tum, t0, tid);
    asm volatile("cp.async.commit_group;");

    for (int j = 0; j < J; j++) {
        __syncthreads();   // buffer (j+1)&1 free: compute(j-1) done by all warps
        if (j + 1 < J) {
            issue_stage(smb, (j + 1) & 1, (sp + (j + 1) * NSPLIT) * KT2, tum, t0, tid);
            asm volatile("cp.async.commit_group;");
            asm volatile("cp.async.wait_group 1;");   // in-order: group j retired
        } else {
            asm volatile("cp.async.wait_group 0;");
        }
        __syncthreads();
        compute_stage(sm, j & 1, acc, w, g, cc);
    }

    // ---- epilogue: write partials [sp][t][40] (R6 exact) ----
    float* part = g_part + (size_t)sp * TPAD * NF;
#pragma unroll
    for (int mh = 0; mh < 2; mh++) {
        int tA = t0 + 32 * w + 16 * mh + g;
#pragma unroll
        for (int nb = 0; nb < 5; nb++) {
            int col = nb * 8 + 2 * cc;
            if (tA < TN)
                *(float2*)(&part[(size_t)tA * NF + col]) =
                    make_float2(acc[mh][nb][0], acc[mh][nb][1]);
            if (tA + 8 < TN)
                *(float2*)(&part[(size_t)(tA + 8) * NF + col]) =
                    make_float2(acc[mh][nb][2], acc[mh][nb][3]);
        }
    }

    // ---- fused finalize: last CTA per mb, COALESCED reduction ----
    __threadfence();                       // publish partials
    __syncthreads();
    if (tid == 0) s_last = atomicAdd(&g_done[mb], 1u);
    __syncthreads();
    if (s_last != NSPLIT - 1) return;
    if (tid == 0) atomicExch(&g_done[mb], 0u);   // self-clean for next replay

    // each (sp) block for this mb = 5120 contiguous floats at g_part[sp*TPAD*40 + t0*40]
    // thread accumulates float4 positions j*128+tid (identical across sp)
    float4 a4[10];
#pragma unroll
    for (int j = 0; j < 10; j++) a4[j] = make_float4(0.f, 0.f, 0.f, 0.f);
#pragma unroll
    for (int k = 0; k < NSPLIT; k++) {
        const float4* blk = (const float4*)(g_part + ((size_t)k * TPAD + t0) * NF);
#pragma unroll
        for (int j = 0; j < 10; j++) {
            float4 v = blk[j * 128 + tid];
            a4[j].x += v.x; a4[j].y += v.y; a4[j].z += v.z; a4[j].w += v.w;
        }
    }
    // smem transpose: 5120 floats [team_local][40]
    float4* smf4 = (float4*)sm;
    __syncthreads();                       // all smem stage reads long done; reuse
#pragma unroll
    for (int j = 0; j < 10; j++) smf4[j * 128 + tid] = a4[j];
    __syncthreads();
    const float* smf = (const float*)sm;

    // coalesced output: block = teams t0..t0+nt-1, 52 cols each, contiguous in out
    const int nt = (t0 + MB <= TN) ? MB : (TN - t0);
    const int total = nt * OUTC;
    float* ob = out + (size_t)t0 * OUTC;
    const float* tsb = T_static + (size_t)t0 * TF;
    for (int q = tid; q < total; q += NTHR) {
        int tl = q / OUTC;
        int c = q - tl * OUTC;
        float v;
        if (c < TF) {
            v = tsb[tl * TF + c];
        } else {
            v = smf[tl * NF + (c - TF)] / smf[tl * NF + 36];
        }
        ob[q] = v;
    }
}

extern "C" void kernel_launch(void* const* d_in, const int* in_sizes, int n_in,
                              void* d_out, int out_size) {
    const float* T_static = (const float*)d_in[0];
    const unsigned int* us = (const unsigned int*)d_in[1];
    const int* tum = (const int*)d_in[2];
    const float* e0 = (const float*)d_in[3];
    const float* e1 = (const float*)d_in[4];
    const float* e2 = (const float*)d_in[5];
    const float* e3 = (const float*)d_in[6];
    const float* e4 = (const float*)d_in[7];
    const float* e5 = (const float*)d_in[8];
    float* out = (float*)d_out;

    cudaFuncSetAttribute(accum_kernel, cudaFuncAttributeMaxDynamicSharedMemorySize,
                         SMEM_TOTAL);
    prep_kernel<<<KPAD / 64, 256>>>(us, e0, e1, e2, e3, e4, e5);
    accum_kernel<<<NMB * NSPLIT, NTHR, SMEM_TOTAL>>>(tum, T_static, out);
}

// round 17
// speedup vs baseline: 1.4241x; 1.4241x over previous
#include <cuda_runtime.h>
#include <cuda_bf16.h>
#include <stdint.h>

#define TN 2000
#define UN 50000
#define TF 16
#define OUTC (TF + 36)
#define NF 40                   // padded features: 0..35 emb, 36 count, 37..39 zero
#define KPAD 50176              // mult of 64
#define KT2 64                  // K per pipeline stage
#define NST_TOT (KPAD / KT2)    // 784
#define MB 128                  // M per CTA (4 warps x m32)
#define NMB 16
#define TPAD (NMB * MB)         // 2048
#define NSPLIT 18               // grid = 288 CTAs ~ 2/SM
#define NTHR 128
#define ASTR 72                              // A row stride (ints): conflict-free
#define ASTAGE_B (128 * ASTR * 4)            // 36864 B
#define BSTR 40                              // B row stride (words): conflict-free
#define BSTAGE_B (NF * BSTR * 4)             // 6400 B
#define SMEM_TOTAL (2 * (ASTAGE_B + BSTAGE_B))   // 86528 B
#define PROW (NSPLIT * NF)                   // 720 floats per team, contiguous

// ---------------- device scratch (static) ----------------
__device__ __nv_bfloat16 g_UT[(size_t)NF * KPAD];   // paired-word layout per 64k block
__device__ float g_part[(size_t)TPAD * PROW];        // [t][sp][40]

__device__ __forceinline__ uint32_t smem_u32(const void* p) {
    uint32_t a;
    asm("{ .reg .u64 t; cvta.to.shared.u64 t, %1; cvt.u32.u64 %0, t; }" : "=r"(a) : "l"(p));
    return a;
}
__device__ __forceinline__ void mma16816(float* c, uint32_t a0, uint32_t a1,
                                         uint32_t a2, uint32_t a3,
                                         uint32_t b0, uint32_t b1) {
    asm volatile("mma.sync.aligned.m16n8k16.row.col.f32.bf16.bf16.f32 "
                 "{%0,%1,%2,%3}, {%4,%5,%6,%7}, {%8,%9}, {%0,%1,%2,%3};"
                 : "+f"(c[0]), "+f"(c[1]), "+f"(c[2]), "+f"(c[3])
                 : "r"(a0), "r"(a1), "r"(a2), "r"(a3), "r"(b0), "r"(b1));
}
__device__ __forceinline__ uint32_t pk(int2 m) {
    return (uint32_t)(m.x + (m.y << 16)) * 0x3F80u;
}

// ---------------- prep: R6 exact (frozen) ----------------
__global__ void prep_kernel(const unsigned int* __restrict__ us,
                            const float* __restrict__ e0, const float* __restrict__ e1,
                            const float* __restrict__ e2, const float* __restrict__ e3,
                            const float* __restrict__ e4, const float* __restrict__ e5) {
    __shared__ float sT[NF * 64];
    int u0 = blockIdx.x * 64;
    int tid = threadIdx.x;
    if (tid < 64) {
        int u = u0 + tid;
        if (u < UN) {
            unsigned probe = 0;
#pragma unroll
            for (int w = 1; w < 32; w += 2) probe |= us[w];
            bool is64 = (probe == 0u);   // int64 serialization -> zero high words
            const float* tabs[6] = {e0, e1, e2, e3, e4, e5};
#pragma unroll
            for (int i = 0; i < 6; i++) {
                int elem = u * 6 + i;
                unsigned idx = us[is64 ? (2 * elem) : elem];
                const float* row = tabs[i] + (size_t)idx * 6;
#pragma unroll
                for (int j = 0; j < 6; j++) sT[(i * 6 + j) * 64 + tid] = row[j];
            }
            sT[36 * 64 + tid] = 1.0f;
        } else {
#pragma unroll
            for (int f = 0; f < 37; f++) sT[f * 64 + tid] = 0.0f;
        }
        sT[37 * 64 + tid] = 0.0f;
        sT[38 * 64 + tid] = 0.0f;
        sT[39 * 64 + tid] = 0.0f;
    }
    __syncthreads();
    for (int idx = tid; idx < NF * 32; idx += blockDim.x) {
        int f = idx >> 5, p = idx & 31;
        int wp = ((p >> 3) << 3) + ((p & 3) << 1) + ((p >> 2) & 1);
        __nv_bfloat162 v = __floats2bfloat162_rn(sT[f * 64 + 2 * p], sT[f * 64 + 2 * p + 1]);
        *(__nv_bfloat162*)(&g_UT[(size_t)f * KPAD + u0 + 2 * wp]) = v;
    }
}

// ---------------- accum: R6 exact (frozen) ----------------
__device__ __forceinline__ void issue_stage(uint32_t smb, int s, int k0,
                                            const int* __restrict__ tum,
                                            int t0, int tid) {
    uint32_t aB = smb + s * ASTAGE_B;
    uint32_t bB = smb + 2 * ASTAGE_B + s * BSTAGE_B;
#pragma unroll
    for (int i = 0; i < 16; i++) {
        int q = tid + i * NTHR;
        int r = q >> 4;
        int c = (q & 15) << 2;
        uint32_t dst = aB + (uint32_t)r * (ASTR * 4) + (uint32_t)(q & 15) * 16u;
        const int* src = tum + (size_t)(t0 + r) * UN + (k0 + c);
        uint32_t sz = ((t0 + r) < TN && (k0 + c) < UN) ? 16u : 0u;
        asm volatile("cp.async.cg.shared.global [%0], [%1], 16, %2;"
                     :: "r"(dst), "l"(src), "r"(sz));
    }
#pragma unroll
    for (int i = 0; i < 3; i++) {
        int q = tid + i * NTHR;
        if (q < NF * 8) {
            int r = q >> 3;
            uint32_t dst = bB + (uint32_t)r * (BSTR * 4) + (uint32_t)(q & 7) * 16u;
            const __nv_bfloat16* src = g_UT + (size_t)r * KPAD + k0 + (q & 7) * 8;
            asm volatile("cp.async.cg.shared.global [%0], [%1], 16, 16;"
                         :: "r"(dst), "l"(src));
        }
    }
}

__device__ __forceinline__ void compute_stage(const char* sm, int s, float acc[2][5][4],
                                              int w, int g, int cc) {
    const int* aP = (const int*)(sm + s * ASTAGE_B);
    const uint32_t* bP = (const uint32_t*)(sm + 2 * ASTAGE_B + s * BSTAGE_B);
    const int rowA = (32 * w + g) * ASTR + 2 * cc;
#pragma unroll
    for (int ks = 0; ks < 4; ks++) {
        uint32_t bf[10];
        const uint32_t* bb = bP + g * BSTR + ks * 8 + cc * 2;
#pragma unroll
        for (int nb = 0; nb < 5; nb++) {
            uint2 v = *(const uint2*)(bb + nb * 8 * BSTR);
            bf[2 * nb] = v.x;
            bf[2 * nb + 1] = v.y;
        }
#pragma unroll
        for (int mh = 0; mh < 2; mh++) {
            const int* p0 = aP + rowA + mh * 16 * ASTR + 16 * ks;
            int2 x0 = *(const int2*)(p0);
            int2 x2 = *(const int2*)(p0 + 8);
            int2 x1 = *(const int2*)(p0 + 8 * ASTR);
            int2 x3 = *(const int2*)(p0 + 8 * ASTR + 8);
            uint32_t a0 = pk(x0), a1 = pk(x1), a2 = pk(x2), a3 = pk(x3);
#pragma unroll
            for (int nb = 0; nb < 5; nb++)
                mma16816(acc[mh][nb], a0, a1, a2, a3, bf[2 * nb], bf[2 * nb + 1]);
        }
    }
}

__global__ void __launch_bounds__(NTHR, 2) accum_kernel(const int* __restrict__ tum) {
    extern __shared__ char sm[];
    const int tid = threadIdx.x;
    const int w = tid >> 5, lane = tid & 31;
    const int g = lane >> 2, cc = lane & 3;
    const int mb = blockIdx.x & (NMB - 1);
    const int sp = blockIdx.x >> 4;
    const int t0 = mb * MB;
    const uint32_t smb = smem_u32(sm);

    const int J = (NST_TOT - sp + NSPLIT - 1) / NSPLIT;

    float acc[2][5][4];
#pragma unroll
    for (int mh = 0; mh < 2; mh++)
#pragma unroll
        for (int nb = 0; nb < 5; nb++)
#pragma unroll
            for (int q = 0; q < 4; q++) acc[mh][nb][q] = 0.0f;

    issue_stage(smb, 0, sp * KT2, tum, t0, tid);
    asm volatile("cp.async.commit_group;");

    for (int j = 0; j < J; j++) {
        __syncthreads();   // buffer (j+1)&1 free: compute(j-1) done by all warps
        if (j + 1 < J) {
            issue_stage(smb, (j + 1) & 1, (sp + (j + 1) * NSPLIT) * KT2, tum, t0, tid);
            asm volatile("cp.async.commit_group;");
            asm volatile("cp.async.wait_group 1;");   // in-order: group j retired
        } else {
            asm volatile("cp.async.wait_group 0;");
        }
        __syncthreads();
        compute_stage(sm, j & 1, acc, w, g, cc);
    }

    // ---- epilogue: write partials, transposed layout [t][sp][40] ----
    float* part = g_part + (size_t)sp * NF;   // + t*PROW + col
#pragma unroll
    for (int mh = 0; mh < 2; mh++) {
        int tA = t0 + 32 * w + 16 * mh + g;
#pragma unroll
        for (int nb = 0; nb < 5; nb++) {
            int col = nb * 8 + 2 * cc;
            if (tA < TN)
                *(float2*)(&part[(size_t)tA * PROW + col]) =
                    make_float2(acc[mh][nb][0], acc[mh][nb][1]);
            if (tA + 8 < TN)
                *(float2*)(&part[(size_t)(tA + 8) * PROW + col]) =
                    make_float2(acc[mh][nb][2], acc[mh][nb][3]);
        }
    }
}

// ---------------- finalize v2: warp per team, fully coalesced ----------------
__global__ void __launch_bounds__(128) finalize_kernel(const float* __restrict__ T_static,
                                                       float* __restrict__ out) {
    __shared__ float smf[4 * PROW];          // 4 teams x 720 floats = 11.5 KB
    const int tid = threadIdx.x;
    const int t0 = blockIdx.x * 4;           // grid 500, 2000 = 500*4 exactly
    // load 4*720 floats = 720 float4, coalesced
    const float4* src = (const float4*)(g_part + (size_t)t0 * PROW);
    float4* d4 = (float4*)smf;
#pragma unroll
    for (int i = 0; i < 6; i++) {
        int q = tid + i * 128;
        if (q < 720) d4[q] = src[q];
    }
    __syncthreads();
    const int wt = tid >> 5, lane = tid & 31;   // warp = team
    const float* base = smf + wt * PROW;
    float s0 = 0.0f, s1 = 0.0f;
#pragma unroll
    for (int k = 0; k < NSPLIT; k++) {
        s0 += base[k * NF + lane];                       // cols 0..31
        if (lane < 8) s1 += base[k * NF + 32 + lane];    // cols 32..39 (36 = count)
    }
    const float cnt = __shfl_sync(0xffffffffu, s1, 4);   // col 36
    const float inv = 1.0f / cnt;
    float* o = out + (size_t)(t0 + wt) * OUTC;
    const float* ts = T_static + (size_t)(t0 + wt) * TF;
    if (lane < TF) o[lane] = ts[lane];
    o[TF + lane] = s0 * inv;                 // emb cols 0..31
    if (lane < 4) o[TF + 32 + lane] = s1 * inv;   // emb cols 32..35
}

extern "C" void kernel_launch(void* const* d_in, const int* in_sizes, int n_in,
                              void* d_out, int out_size) {
    const float* T_static = (const float*)d_in[0];
    const unsigned int* us = (const unsigned int*)d_in[1];
    const int* tum = (const int*)d_in[2];
    const float* e0 = (const float*)d_in[3];
    const float* e1 = (const float*)d_in[4];
    const float* e2 = (const float*)d_in[5];
    const float* e3 = (const float*)d_in[6];
    const float* e4 = (const float*)d_in[7];
    const float* e5 = (const float*)d_in[8];
    float* out = (float*)d_out;

    cudaFuncSetAttribute(accum_kernel, cudaFuncAttributeMaxDynamicSharedMemorySize,
                         SMEM_TOTAL);
    prep_kernel<<<KPAD / 64, 256>>>(us, e0, e1, e2, e3, e4, e5);
    accum_kernel<<<NMB * NSPLIT, NTHR, SMEM_TOTAL>>>(tum);
    finalize_kernel<<<TN / 4, 128>>>(T_static, out);
}